// round 13
// baseline (speedup 1.0000x reference)
#include <cuda_runtime.h>
#include <cuda_bf16.h>

#define NGRID   10000
#define NSTEPS  730
#define LENF    15
#define NEARZEROF 1e-5f
#define UNR     5          // 730 % 10 == 0 (ping-pong pairs)

// scratch for raw discharge q: row 0 is a dummy (phantom response target),
// Q[t] lives at row t+1.
__device__ float g_Q[(size_t)(NSTEPS + 1) * NGRID];

__device__ __forceinline__ float fast_lg2(float x) {
    float r; asm("lg2.approx.f32 %0, %1;" : "=f"(r) : "f"(x)); return r;
}
__device__ __forceinline__ float fast_ex2(float x) {
    float r; asm("ex2.approx.f32 %0, %1;" : "=f"(r) : "f"(x)); return r;
}

// ---------------------------------------------------------------------------
// Kernel 1: sequential HBV scan, one thread per cell.
// ---------------------------------------------------------------------------
__global__ __launch_bounds__(64, 1)
void hbv_scan_kernel(const float* __restrict__ x_phy,   // [NSTEPS, NGRID, 3]
                     const float* __restrict__ phy)     // [NGRID, 16]
{
    int g = blockIdx.x * blockDim.x + threadIdx.x;
    if (g >= NGRID) return;

    const float* ps = phy + g * 16;
    float BETA   = ps[0]  * 5.0f   + 1.0f;
    float FC     = ps[1]  * 950.0f + 50.0f;
    float K0     = ps[2]  * 0.85f  + 0.05f;
    float K1     = ps[3]  * 0.49f  + 0.01f;
    float K2     = ps[4]  * 0.199f + 0.001f;
    float LP     = ps[5]  * 0.8f   + 0.2f;
    float PERC   = ps[6]  * 10.0f;
    float UZL    = ps[7]  * 100.0f;
    float TT     = ps[8]  * 5.0f   - 2.5f;
    float CFMAX  = ps[9]  * 9.5f   + 0.5f;
    float CFR    = ps[10] * 0.1f;
    float CWH    = ps[11] * 0.2f;
    float BETAET = ps[12] * 4.7f   + 0.3f;
    float C      = ps[13];

    float invFC    = 1.0f / FC;
    float invLPFC  = 1.0f / (LP * FC);
    float CFRCFMAX = CFR * CFMAX;
    // folded log constants: pow(x*c, b) = ex2(b*lg2(x) + b*log2(c))
    float CA = BETA   * fast_lg2(invFC);
    float CE = BETAET * fast_lg2(invLPFC);
    // response constants
    float omK0  = 1.0f - K0;
    float omK1  = 1.0f - K1;
    float omK2  = 1.0f - K2;
    float K0UZL = K0 * UZL;

    // ---- state; (suz, slz) pre-inverted so the phantom first response
    //      lands exactly on (NEARZERO, NEARZERO) ----
    float snow = NEARZEROF, melt = NEARZEROF, sm = NEARZEROF;
    float s3t   = NEARZEROF / omK1;                        // target suz3
    float suz   = fmaxf(s3t, (s3t - K0UZL) / omK0) + PERC; // phantom suz1
    float slz   = NEARZEROF / omK2 - PERC;                 // phantom slz0
    float rex   = 0.0f;                                    // deferred recharge+excess

    const int rowstride = NGRID * 3;
    const float* xbase = x_phy + (size_t)g * 3;
    float* qptr = g_Q + g;      // phantom writes row 0; q_t -> row t+1

    float Ap[UNR], Atm[UNR], Ape[UNR];
    float Bp[UNR], Btm[UNR], Bpe[UNR];

#define LOADG(P, T, E, GRP)                                             \
    _Pragma("unroll")                                                   \
    for (int u = 0; u < UNR; u++) {                                     \
        int idx = (GRP) * UNR + u;                                      \
        if (idx >= NSTEPS) idx = NSTEPS - 1;                            \
        const float* xn = xbase + (size_t)idx * rowstride;              \
        P[u] = __ldg(xn + 0); T[u] = __ldg(xn + 1); E[u] = __ldg(xn + 2); \
    }

// deferred response for the previous step: consumes rex, updates suz/slz,
// stores q_{prev}.
#define RESPONSE()                                                      \
    {                                                                   \
        float suz1    = suz + rex;                                      \
        float suz2    = fmaxf(suz1 - PERC, 0.0f);                       \
        float percact = suz1 - suz2;                                    \
        float suz3    = fminf(suz2, fmaf(omK0, suz2, K0UZL));           \
        suz           = omK1 * suz3;                                    \
        float slz1    = slz + percact;                                  \
        slz           = omK2 * slz1;                                    \
        *qptr = (suz2 - suz) + (slz1 - slz);                            \
        qptr += NGRID;                                                  \
    }

#define STEPS(P, T, E)                                                  \
    _Pragma("unroll")                                                   \
    for (int u = 0; u < UNR; u++) {                                     \
        float p  = P[u];                                                \
        float tm = T[u];                                                \
        float pe = E[u];                                                \
        /* input-only precomputes */                                    \
        float rain     = (tm >= TT) ? p : 0.0f;                         \
        float snowfall = p - rain;                                      \
        float mpot     = fmaxf(CFMAX    * (tm - TT), 0.0f);             \
        float rpot     = fmaxf(CFRCFMAX * (TT - tm), 0.0f);             \
        /* pow #1 issues first; snow chain + response fill its shadow */ \
        float soil_wet = fminf(fast_ex2(fmaf(BETA, fast_lg2(sm), CA)), 1.0f); \
        /* snow bucket (min-form) */                                    \
        float sp     = snow + snowfall;                                 \
        float m      = fminf(mpot, sp);                                 \
        float snow1  = sp - m;                                          \
        float melt1  = melt + m;                                        \
        float refr   = fminf(rpot, melt1);                              \
        float melt2  = melt1 - refr;                                    \
        snow         = snow1 + refr;                                    \
        float tosoil = fmaxf(fmaf(-CWH, snow, melt2), 0.0f);            \
        melt         = melt2 - tosoil;                                  \
        /* ---- deferred response of step u-1 (independent filler) ---- */ \
        RESPONSE()                                                      \
        /* capillary coefficients from post-response slz */             \
        float cslz    = C * slz;                                        \
        float om_kcap = fmaf(-cslz, invFC, 1.0f);                       \
        /* soil bucket */                                               \
        float rt       = rain + tosoil;                                 \
        float smrt     = sm + rt;                                       \
        float recharge = rt * soil_wet;                                 \
        float sm_pre   = fmaf(-rt, soil_wet, smrt);                     \
        float sm_c     = fminf(sm_pre, FC);                             \
        float excess   = sm_pre - sm_c;                                 \
        rex            = recharge + excess;   /* deferred to next step */ \
        float evapfac  = fminf(fast_ex2(fmaf(BETAET, fast_lg2(sm_pre), CE)), 1.0f); \
        float sm_et    = fmaxf(fmaf(-pe, evapfac, sm_c), NEARZEROF);    \
        float sm_a     = fmaf(sm_et, om_kcap, cslz);                    \
        float sm_b     = sm_et + slz;                                   \
        sm             = fminf(sm_a, sm_b);                             \
        float cap      = sm - sm_et;                                    \
        slz            = fmaxf(slz - cap, NEARZEROF);                   \
    }

    LOADG(Ap, Atm, Ape, 0)
    LOADG(Bp, Btm, Bpe, 1)

    for (int base = 0; base < NSTEPS; base += 2 * UNR) {
        int grp = base / UNR;
        STEPS(Ap, Atm, Ape)
        LOADG(Ap, Atm, Ape, grp + 2)
        STEPS(Bp, Btm, Bpe)
        LOADG(Bp, Btm, Bpe, grp + 3)
    }

    // epilogue: response + store for the final step (row NSTEPS)
    RESPONSE()

#undef LOADG
#undef RESPONSE
#undef STEPS
}

// ---------------------------------------------------------------------------
// Kernel 2: gamma routing, staged register prefetch (chunks of 15).
// Reads Q[t] from g_Q row t+1. y0 = tile offset (launch sliced into 4 parts
// so ncu -s 5 -c 1 lands on the SCAN kernel of the next call).
// ---------------------------------------------------------------------------
#define TTILE 75
#define NCHUNK (TTILE / LENF)   // 5

__global__ __launch_bounds__(128, 1)
void hbv_rout_kernel(const float* __restrict__ phy,   // [NGRID, 16]
                     float* __restrict__ out,         // [NSTEPS, NGRID]
                     int y0)
{
    int g = blockIdx.x * blockDim.x + threadIdx.x;
    if (g >= NGRID) return;

    // ln(k + 0.5), k = 0..14
    const float LOGTG[LENF] = {
        -0.69314718f, 0.40546511f, 0.91629073f, 1.25276297f, 1.50407740f,
         1.70474809f, 1.87180218f, 2.01490302f, 2.14006616f, 2.25129180f,
         2.35137526f, 2.44234704f, 2.52572864f, 2.60268969f, 2.67418505f };

    float aa    = fmaxf(phy[g * 16 + 14] * 2.9f, 0.0f) + 0.1f;
    float theta = fmaxf(phy[g * 16 + 15] * 6.5f, 0.0f) + 0.5f;
    float invTheta = 1.0f / theta;
    float am1 = aa - 1.0f;

    float w[LENF];
    float wsum = 0.0f;
#pragma unroll
    for (int k = 0; k < LENF; k++) {
        float tg = (float)k + 0.5f;
        float e = expf(fmaf(am1, LOGTG[k], -tg * invTheta));
        w[k] = e;
        wsum += e;
    }
    float invw = 1.0f / wsum;
#pragma unroll
    for (int k = 0; k < LENF; k++) w[k] *= invw;

    int t0 = (y0 + blockIdx.y) * TTILE;   // multiple of 15
    const float* qcol = g_Q + NGRID + g;  // Q[t] at row t+1
    float* ocol = out + g;

    // circular history: h[tau % 15] holds Q[tau]; t0 % 15 == 0.
    float h[LENF];
#pragma unroll
    for (int j = 0; j < LENF - 1; j++) {
        int t = t0 - (LENF - 1) + j;      // slot (t % 15) = j+1
        h[j + 1] = (t >= 0) ? __ldg(qcol + (size_t)t * NGRID) : 0.0f;
    }
    h[0] = 0.0f;

    // batched preload of chunk 0 (MLP = 15)
    float buf[LENF], nxt[LENF];
#pragma unroll
    for (int i = 0; i < LENF; i++) {
        int t = t0 + i;
        if (t > NSTEPS - 1) t = NSTEPS - 1;
        buf[i] = __ldg(qcol + (size_t)t * NGRID);
    }

#pragma unroll
    for (int ch = 0; ch < NCHUNK; ch++) {
        // prefetch chunk ch+1 (clamped; overlaps compute)
#pragma unroll
        for (int i = 0; i < LENF; i++) {
            int t = t0 + (ch + 1) * LENF + i;
            if (t > NSTEPS - 1) t = NSTEPS - 1;
            nxt[i] = __ldg(qcol + (size_t)t * NGRID);
        }
        // compute 15 outputs; slot of (t0+ch*15+i) is i
#pragma unroll
        for (int i = 0; i < LENF; i++) {
            h[i] = buf[i];
            float qr = 0.0f;
#pragma unroll
            for (int k = 0; k < LENF; k++) {
                qr = fmaf(w[k], h[(i - k + LENF) % LENF], qr);
            }
            int t = t0 + ch * LENF + i;
            if (t < NSTEPS) ocol[(size_t)t * NGRID] = qr;
        }
#pragma unroll
        for (int i = 0; i < LENF; i++) buf[i] = nxt[i];
    }
}

extern "C" void kernel_launch(void* const* d_in, const int* in_sizes, int n_in,
                              void* d_out, int out_size) {
    const float* x_phy = (const float*)d_in[0];
    const float* phy   = (const float*)d_in[1];
    float* out         = (float*)d_out;
    (void)in_sizes; (void)n_in; (void)out_size;

    // scan: 1 cell/thread, 64-thread blocks -> 157 blocks over 148 SMs
    hbv_scan_kernel<<<(NGRID + 63) / 64, 64>>>(x_phy, phy);

    // routing split into 4 slices (total 10 y-tiles) -> 5 launches per call,
    // so ncu (-s 5 -c 1) captures the SCAN kernel of the next call.
    dim3 gx((NGRID + 127) / 128, 3);
    hbv_rout_kernel<<<gx, 128>>>(phy, out, 0);
    hbv_rout_kernel<<<gx, 128>>>(phy, out, 3);
    hbv_rout_kernel<<<gx, 128>>>(phy, out, 6);
    dim3 gy((NGRID + 127) / 128, 1);
    hbv_rout_kernel<<<gy, 128>>>(phy, out, 9);
}

// round 14
// speedup vs baseline: 1.4636x; 1.4636x over previous
#include <cuda_runtime.h>
#include <cuda_bf16.h>

#define NGRID   10000
#define NSTEPS  730
#define LENF    15
#define NEARZEROF 1e-5f
#define UNR     5

__device__ __forceinline__ float fast_lg2(float x) {
    float r; asm("lg2.approx.f32 %0, %1;" : "=f"(r) : "f"(x)); return r;
}
__device__ __forceinline__ float fast_ex2(float x) {
    float r; asm("ex2.approx.f32 %0, %1;" : "=f"(r) : "f"(x)); return r;
}

// ---------------------------------------------------------------------------
// Fused HBV scan + gamma routing. One thread per cell, single launch.
// 15-step macro tiles -> compile-time circular-buffer slots for routing.
// ---------------------------------------------------------------------------
__global__ __launch_bounds__(64, 1)
void hbv_fused_kernel(const float* __restrict__ x_phy,   // [NSTEPS, NGRID, 3]
                      const float* __restrict__ phy,     // [NGRID, 16]
                      float* __restrict__ out)           // [NSTEPS, NGRID]
{
    int g = blockIdx.x * blockDim.x + threadIdx.x;
    if (g >= NGRID) return;

    const float* ps = phy + g * 16;
    float BETA   = ps[0]  * 5.0f   + 1.0f;
    float FC     = ps[1]  * 950.0f + 50.0f;
    float K0     = ps[2]  * 0.85f  + 0.05f;
    float K1     = ps[3]  * 0.49f  + 0.01f;
    float K2     = ps[4]  * 0.199f + 0.001f;
    float LP     = ps[5]  * 0.8f   + 0.2f;
    float PERC   = ps[6]  * 10.0f;
    float UZL    = ps[7]  * 100.0f;
    float TT     = ps[8]  * 5.0f   - 2.5f;
    float CFMAX  = ps[9]  * 9.5f   + 0.5f;
    float CFR    = ps[10] * 0.1f;
    float CWH    = ps[11] * 0.2f;
    float BETAET = ps[12] * 4.7f   + 0.3f;
    float C      = ps[13];
    float aa     = fmaxf(ps[14] * 2.9f, 0.0f) + 0.1f;
    float theta  = fmaxf(ps[15] * 6.5f, 0.0f) + 0.5f;

    float invFC    = 1.0f / FC;
    float invLPFC  = 1.0f / (LP * FC);
    float CFRCFMAX = CFR * CFMAX;
    float CA = BETA   * fast_lg2(invFC);     // folded pow constants
    float CE = BETAET * fast_lg2(invLPFC);
    float omK0  = 1.0f - K0;
    float omK1  = 1.0f - K1;
    float omK2  = 1.0f - K2;
    float K0UZL = K0 * UZL;

    // ---- routing weights (gammaln & a*log(theta) cancel under norm) ----
    const float LOGTG[LENF] = {
        -0.69314718f, 0.40546511f, 0.91629073f, 1.25276297f, 1.50407740f,
         1.70474809f, 1.87180218f, 2.01490302f, 2.14006616f, 2.25129180f,
         2.35137526f, 2.44234704f, 2.52572864f, 2.60268969f, 2.67418505f };
    float invTheta = 1.0f / theta;
    float am1 = aa - 1.0f;
    float w[LENF];
    float wsum = 0.0f;
#pragma unroll
    for (int k = 0; k < LENF; k++) {
        float tg = (float)k + 0.5f;
        float e = expf(fmaf(am1, LOGTG[k], -tg * invTheta));
        w[k] = e;
        wsum += e;
    }
    float invw = 1.0f / wsum;
#pragma unroll
    for (int k = 0; k < LENF; k++) w[k] *= invw;

    // ---- state ----
    float snow = NEARZEROF, melt = NEARZEROF, sm = NEARZEROF,
          suz = NEARZEROF, slz = NEARZEROF;
    float cslz    = C * slz;
    float om_kcap = fmaf(-cslz, invFC, 1.0f);

    // circular history: hist[t % 15] = q_t; q_{t<0} = 0
    float hist[LENF];
#pragma unroll
    for (int k = 0; k < LENF; k++) hist[k] = 0.0f;

    const int rowstride = NGRID * 3;
    const float* xbase = x_phy + (size_t)g * 3;
    float* ocol = out + g;

    float Ap[UNR], Atm[UNR], Ape[UNR];
    float Bp[UNR], Btm[UNR], Bpe[UNR];
    float Cp[UNR], Ctm[UNR], Cpe[UNR];

#define LOADG(P, T, E, GRP)                                             \
    _Pragma("unroll")                                                   \
    for (int u = 0; u < UNR; u++) {                                     \
        int idx = (GRP) * UNR + u;                                      \
        if (idx >= NSTEPS) idx = NSTEPS - 1;                            \
        const float* xn = xbase + (size_t)idx * rowstride;              \
        P[u] = __ldg(xn + 0); T[u] = __ldg(xn + 1); E[u] = __ldg(xn + 2); \
    }

// 5 steps; PH = compile-time phase (0,5,10) -> all hist indices static.
#define STEPS(P, T, E, BASE, PH)                                        \
    _Pragma("unroll")                                                   \
    for (int u = 0; u < UNR; u++) {                                     \
        float p  = P[u];                                                \
        float tm = T[u];                                                \
        float pe = E[u];                                                \
        /* input-only precomputes */                                    \
        float rain     = (tm >= TT) ? p : 0.0f;                         \
        float snowfall = p - rain;                                      \
        float mpot     = fmaxf(CFMAX    * (tm - TT), 0.0f);             \
        float rpot     = fmaxf(CFRCFMAX * (TT - tm), 0.0f);             \
        /* pow #1 (MUFU shadow filled by snow chain + routing) */       \
        float soil_wet = fminf(fast_ex2(fmaf(BETA, fast_lg2(sm), CA)), 1.0f); \
        /* snow bucket (min-form) */                                    \
        float sp     = snow + snowfall;                                 \
        float m      = fminf(mpot, sp);                                 \
        float snow1  = sp - m;                                          \
        float melt1  = melt + m;                                        \
        float refr   = fminf(rpot, melt1);                              \
        float melt2  = melt1 - refr;                                    \
        snow         = snow1 + refr;                                    \
        float tosoil = fmaxf(fmaf(-CWH, snow, melt2), 0.0f);            \
        melt         = melt2 - tosoil;                                  \
        /* soil bucket (chain-shortened, exact) */                      \
        float rt       = rain + tosoil;                                 \
        float smrt     = sm + rt;                                       \
        float recharge = rt * soil_wet;                                 \
        float sm_pre   = fmaf(-rt, soil_wet, smrt);                     \
        float sm_c     = fminf(sm_pre, FC);                             \
        float excess   = sm_pre - sm_c;                                 \
        float evapfac  = fminf(fast_ex2(fmaf(BETAET, fast_lg2(sm_pre), CE)), 1.0f); \
        float sm_et    = fmaxf(fmaf(-pe, evapfac, sm_c), NEARZEROF);    \
        float sm_a     = fmaf(sm_et, om_kcap, cslz);                    \
        float sm_b     = sm_et + slz;                                   \
        sm             = fminf(sm_a, sm_b);                             \
        float cap      = sm - sm_et;                                    \
        slz            = fmaxf(slz - cap, NEARZEROF);                   \
        /* response (condensed, exact) */                               \
        float suz1    = suz + (recharge + excess);                      \
        float suz2    = fmaxf(suz1 - PERC, 0.0f);                       \
        float percact = suz1 - suz2;                                    \
        float suz3    = fminf(suz2, fmaf(omK0, suz2, K0UZL));           \
        suz           = omK1 * suz3;                                    \
        float slz1    = slz + percact;                                  \
        slz           = omK2 * slz1;                                    \
        float q       = (suz2 - suz) + (slz1 - slz);                    \
        /* next-step capillary coefficients (off-chain) */              \
        cslz    = C * slz;                                              \
        om_kcap = fmaf(-cslz, invFC, 1.0f);                             \
        /* fused routing: compile-time circular indices */              \
        hist[((PH) + u) % LENF] = q;                                    \
        float qr = 0.0f;                                                \
        _Pragma("unroll")                                               \
        for (int k = 0; k < LENF; k++)                                  \
            qr = fmaf(w[k], hist[((PH) + u - k + LENF) % LENF], qr);    \
        ocol[(size_t)((BASE) + u) * NGRID] = qr;                        \
    }

    // prologue: groups 0,1,2
    LOADG(Ap, Atm, Ape, 0)
    LOADG(Bp, Btm, Bpe, 1)
    LOADG(Cp, Ctm, Cpe, 2)

    // 48 macro tiles of 15 steps (groups 3m, 3m+1, 3m+2)
    for (int mt = 0; mt < 48; mt++) {
        int base = mt * 15;
        int grp  = mt * 3;
        STEPS(Ap, Atm, Ape, base,      0)
        LOADG(Ap, Atm, Ape, grp + 3)
        STEPS(Bp, Btm, Bpe, base + 5,  5)
        LOADG(Bp, Btm, Bpe, grp + 4)
        STEPS(Cp, Ctm, Cpe, base + 10, 10)
        LOADG(Cp, Ctm, Cpe, grp + 5)
    }
    // tail: steps 720..729; 720 % 15 == 0 -> phases 0 and 5
    STEPS(Ap, Atm, Ape, 720, 0)
    STEPS(Bp, Btm, Bpe, 725, 5)

#undef LOADG
#undef STEPS
}

extern "C" void kernel_launch(void* const* d_in, const int* in_sizes, int n_in,
                              void* d_out, int out_size) {
    const float* x_phy = (const float*)d_in[0];
    const float* phy   = (const float*)d_in[1];
    float* out         = (float*)d_out;
    (void)in_sizes; (void)n_in; (void)out_size;

    // 1 cell/thread, 64-thread blocks -> 157 blocks over 148 SMs
    hbv_fused_kernel<<<(NGRID + 63) / 64, 64>>>(x_phy, phy, out);
}